// round 16
// baseline (speedup 1.0000x reference)
#include <cuda_runtime.h>
#include <cstdint>

#define POOL 14
#define IMG_H 200
#define IMG_W 200
#define IMG_C 1024
#define NUM_ROIS 512

#define NCHUNK 4                       // 256-ch slices -> 41MB image slice, L2-resident
#define CHUNK_FLOATS (IMG_C / NCHUNK)  // 256 floats per cell-chunk
#define LANES_PER_CELL 16
#define CELLS_PER_BLOCK 16
#define THREADS (LANES_PER_CELL * CELLS_PER_BLOCK)  // 256

typedef unsigned long long u64;

// ---- packed f32x2 helpers (sm_103a) ----
__device__ __forceinline__ u64 pk2(float a, float b) {
    u64 r;
    asm("mov.b64 %0, {%1, %2};" : "=l"(r) : "f"(a), "f"(b));
    return r;
}
__device__ __forceinline__ u64 mul2(u64 a, u64 b) {
    u64 r;
    asm("mul.rn.f32x2 %0, %1, %2;" : "=l"(r) : "l"(a), "l"(b));
    return r;
}
__device__ __forceinline__ u64 fma2(u64 a, u64 b, u64 c) {
    u64 r;
    asm("fma.rn.f32x2 %0, %1, %2, %3;" : "=l"(r) : "l"(a), "l"(b), "l"(c));
    return r;
}

// 256-bit L2-only gather load: 4x packed f32x2 = 8 floats = 32B.
__device__ __forceinline__ void ldg256_cg(const float* p,
                                          u64& r0, u64& r1, u64& r2, u64& r3) {
    asm volatile("ld.global.cg.v4.b64 {%0,%1,%2,%3}, [%4];"
                 : "=l"(r0), "=l"(r1), "=l"(r2), "=l"(r3) : "l"(p));
}

// 256-bit streaming store (evict-first: protects the L2-resident image slice).
__device__ __forceinline__ void stg256_cs(float* p, u64 r0, u64 r1, u64 r2, u64 r3) {
    asm volatile("st.global.cs.v4.b64 [%0], {%1,%2,%3,%4};"
                 :: "l"(p), "l"(r0), "l"(r1), "l"(r2), "l"(r3) : "memory");
}

// R15 winner with 256-bit memory ops: loads 16->8, stores 4->2 per thread,
// addressing ALU halves; wavefront (data-path) count unchanged. Guarded
// corner loads + unconditional exact-zero lerp chain kept from R15.
__global__ void __launch_bounds__(THREADS, 4)
roi_resize_kernel(const float* __restrict__ img,
                  const int* __restrict__ rois,
                  float* __restrict__ out)
{
    const int cell_local = threadIdx.x >> 4;        // 0..15
    const int c          = threadIdx.x & 15;        // lane within cell (8 floats)

    const int idx  = blockIdx.x * CELLS_PER_BLOCK + cell_local;  // 0..100351
    const int roi  = idx / (POOL * POOL);
    const int cell = idx - roi * (POOL * POOL);
    const int py   = cell / POOL;
    const int px   = cell - py * POOL;

    const int chunk_off = blockIdx.y * CHUNK_FLOATS;

    const int4 box = reinterpret_cast<const int4*>(rois)[roi];
    const int bx = box.x, by = box.y, bw = box.z, bh = box.w;

    // Match reference math: fraction from UNclipped floor.
    const float sy = (float)py * ((float)bh / (float)POOL);
    const float sx = (float)px * ((float)bw / (float)POOL);
    const int y0 = (int)floorf(sy);
    const int x0 = (int)floorf(sx);
    const float wy = sy - (float)y0;
    const float wx = sx - (float)x0;

    const bool need_x1 = (wx != 0.0f);
    const bool need_y1 = (wy != 0.0f);
    const bool need_xy = need_x1 && need_y1;

    const int y0c = min(max(y0, 0), bh - 1);
    const int y1c = min(max(y0 + 1, 0), bh - 1);
    const int x0c = min(max(x0, 0), bw - 1);
    const int x1c = min(max(x0 + 1, 0), bw - 1);

    const int iy0 = by + y0c;
    const int iy1 = by + y1c;
    const int ix0 = bx + x0c;
    const int ix1 = bx + x1c;

    const u64 wx2   = pk2(wx, wx);
    const u64 omwx2 = pk2(1.0f - wx, 1.0f - wx);
    const u64 wy2   = pk2(wy, wy);
    const u64 omwy2 = pk2(1.0f - wy, 1.0f - wy);

    // Lane offset folded once: c*8 floats = c*32B.
    const float* base = img + chunk_off + c * 8;
    const float* __restrict__ p00 = base + ((size_t)iy0 * IMG_W + ix0) * IMG_C;
    const float* __restrict__ p01 = base + ((size_t)iy0 * IMG_W + ix1) * IMG_C;
    const float* __restrict__ p10 = base + ((size_t)iy1 * IMG_W + ix0) * IMG_C;
    const float* __restrict__ p11 = base + ((size_t)iy1 * IMG_W + ix1) * IMG_C;

    float* __restrict__ o = out + (size_t)idx * IMG_C + chunk_off + c * 8;

    // x-lerp of one packed pair; exact for skipped corners (regs==0, weight==0).
#define XLERP(g0, g1) fma2(g1, wx2, mul2(g0, omwx2))

    // Two batches of 128 floats; lane handles 8 contiguous floats per batch.
    // Per batch: <=4 front-batched LDG.256 (16 lanes x 32B = 512B/corner,
    // fully coalesced) + 24 packed ops + 1 STG.256.
#pragma unroll
    for (int h = 0; h < 2; h++) {
        const int foff = h * 128;   // float offset of this batch

        u64 g00a, g00b, g00c, g00d;
        ldg256_cg(p00 + foff, g00a, g00b, g00c, g00d);

        u64 g01a = 0, g01b = 0, g01c = 0, g01d = 0;
        if (need_x1) ldg256_cg(p01 + foff, g01a, g01b, g01c, g01d);

        u64 g10a = 0, g10b = 0, g10c = 0, g10d = 0;
        if (need_y1) ldg256_cg(p10 + foff, g10a, g10b, g10c, g10d);

        u64 g11a = 0, g11b = 0, g11c = 0, g11d = 0;
        if (need_xy) ldg256_cg(p11 + foff, g11a, g11b, g11c, g11d);

        // Unconditional lerp chain — exact even for skipped corners:
        // wx==+0 ==> XLERP(g0, anything)==g0; wy==+0 ==> r==top.
        const u64 ta = XLERP(g00a, g01a);
        const u64 tb = XLERP(g00b, g01b);
        const u64 tc = XLERP(g00c, g01c);
        const u64 td = XLERP(g00d, g01d);

        const u64 ba = XLERP(g10a, g11a);
        const u64 bb = XLERP(g10b, g11b);
        const u64 bc = XLERP(g10c, g11c);
        const u64 bd = XLERP(g10d, g11d);

        const u64 r0 = fma2(ba, wy2, mul2(ta, omwy2));
        const u64 r1 = fma2(bb, wy2, mul2(tb, omwy2));
        const u64 r2 = fma2(bc, wy2, mul2(tc, omwy2));
        const u64 r3 = fma2(bd, wy2, mul2(td, omwy2));

        stg256_cs(o + foff, r0, r1, r2, r3);
    }
#undef XLERP
}

extern "C" void kernel_launch(void* const* d_in, const int* in_sizes, int n_in,
                              void* d_out, int out_size)
{
    const float* img  = (const float*)d_in[0];
    const int*   rois = (const int*)d_in[1];
    if (in_sizes[0] == NUM_ROIS * 4) {  // defensive: swapped order
        rois = (const int*)d_in[0];
        img  = (const float*)d_in[1];
    }
    float* out = (float*)d_out;

    dim3 grid((NUM_ROIS * POOL * POOL) / CELLS_PER_BLOCK, NCHUNK);  // (6272, 4)
    roi_resize_kernel<<<grid, THREADS>>>(img, rois, out);
}

// round 17
// speedup vs baseline: 1.0579x; 1.0579x over previous
#include <cuda_runtime.h>
#include <cstdint>

#define POOL 14
#define IMG_H 200
#define IMG_W 200
#define IMG_C 1024
#define NUM_ROIS 512

#define NCHUNK 4                       // 256-ch slices -> 41MB image slice, L2-resident
#define CHUNK_FLOATS (IMG_C / NCHUNK)  // 256 floats per cell-chunk
#define LANES_PER_CELL 16
#define CELLS_PER_BLOCK 16
#define THREADS (LANES_PER_CELL * CELLS_PER_BLOCK)  // 256

typedef unsigned long long u64;

// ---- packed f32x2 helpers (sm_103a) ----
__device__ __forceinline__ u64 pk2(float a, float b) {
    u64 r;
    asm("mov.b64 %0, {%1, %2};" : "=l"(r) : "f"(a), "f"(b));
    return r;
}
__device__ __forceinline__ u64 mul2(u64 a, u64 b) {
    u64 r;
    asm("mul.rn.f32x2 %0, %1, %2;" : "=l"(r) : "l"(a), "l"(b));
    return r;
}
__device__ __forceinline__ u64 fma2(u64 a, u64 b, u64 c) {
    u64 r;
    asm("fma.rn.f32x2 %0, %1, %2, %3;" : "=l"(r) : "l"(a), "l"(b), "l"(c));
    return r;
}

// 128-bit L2-only load with compile-time byte offset: [reg + imm] addressing,
// zero per-load address ALU (the imm rides in the instruction encoding).
#define LDG128_CG_OFF(p, IMM, lo, hi)                                        \
    asm volatile("ld.global.cg.v2.b64 {%0,%1}, [%2+" #IMM "];"               \
                 : "=l"(lo), "=l"(hi) : "l"(p))

// 128-bit streaming store with compile-time byte offset.
#define STG128_CS_OFF(p, IMM, lo, hi)                                        \
    asm volatile("st.global.cs.v2.b64 [%0+" #IMM "], {%1,%2};"               \
                 :: "l"(p), "l"(lo), "l"(hi) : "memory")

// R15 winner (106.7us: 128-bit ops, 39 regs, occ 63%) + one edit: the lane
// offset (c*16B) is folded into the 5 pointers once, so every load/store in
// the unrolled batches is [reg+literal] (0/256/512/768B) — removing the
// per-load 64-bit address adds that made alu=22% of issue.
__global__ void __launch_bounds__(THREADS, 6)
roi_resize_kernel(const float* __restrict__ img,
                  const int* __restrict__ rois,
                  float* __restrict__ out)
{
    const int cell_local = threadIdx.x >> 4;        // 0..15
    const int c          = threadIdx.x & 15;        // float4 lane within cell

    const int idx  = blockIdx.x * CELLS_PER_BLOCK + cell_local;  // 0..100351
    const int roi  = idx / (POOL * POOL);
    const int cell = idx - roi * (POOL * POOL);
    const int py   = cell / POOL;
    const int px   = cell - py * POOL;

    const int chunk_off = blockIdx.y * CHUNK_FLOATS;

    const int4 box = reinterpret_cast<const int4*>(rois)[roi];
    const int bx = box.x, by = box.y, bw = box.z, bh = box.w;

    // Match reference math: fraction from UNclipped floor.
    const float sy = (float)py * ((float)bh / (float)POOL);
    const float sx = (float)px * ((float)bw / (float)POOL);
    const int y0 = (int)floorf(sy);
    const int x0 = (int)floorf(sx);
    const float wy = sy - (float)y0;
    const float wx = sx - (float)x0;

    const bool need_x1 = (wx != 0.0f);
    const bool need_y1 = (wy != 0.0f);
    const bool need_xy = need_x1 && need_y1;

    const int y0c = min(max(y0, 0), bh - 1);
    const int y1c = min(max(y0 + 1, 0), bh - 1);
    const int x0c = min(max(x0, 0), bw - 1);
    const int x1c = min(max(x0 + 1, 0), bw - 1);

    const int iy0 = by + y0c;
    const int iy1 = by + y1c;
    const int ix0 = bx + x0c;
    const int ix1 = bx + x1c;

    const u64 wx2   = pk2(wx, wx);
    const u64 omwx2 = pk2(1.0f - wx, 1.0f - wx);
    const u64 wy2   = pk2(wy, wy);
    const u64 omwy2 = pk2(1.0f - wy, 1.0f - wy);

    // Lane offset folded ONCE into all pointers: c float4s = c*16 bytes.
    const float* base = img + chunk_off + c * 4;
    const float* __restrict__ p00 = base + ((size_t)iy0 * IMG_W + ix0) * IMG_C;
    const float* __restrict__ p01 = base + ((size_t)iy0 * IMG_W + ix1) * IMG_C;
    const float* __restrict__ p10 = base + ((size_t)iy1 * IMG_W + ix0) * IMG_C;
    const float* __restrict__ p11 = base + ((size_t)iy1 * IMG_W + ix1) * IMG_C;

    float* __restrict__ o = out + (size_t)idx * IMG_C + chunk_off + c * 4;

    // x-lerp of one packed pair; exact for skipped corners (regs==0, weight==0).
#define XLERP(g0, g1) fma2(g1, wx2, mul2(g0, omwx2))

    // Batch macro: all addresses are [ptr + literal]. F0/F1 are byte offsets.
#define BATCH(F0, F1)                                                        \
    {                                                                        \
        u64 a00l, a00h, b00l, b00h;                                          \
        LDG128_CG_OFF(p00, F0, a00l, a00h);                                  \
        LDG128_CG_OFF(p00, F1, b00l, b00h);                                  \
        u64 a01l = 0, a01h = 0, b01l = 0, b01h = 0;                          \
        if (need_x1) {                                                       \
            LDG128_CG_OFF(p01, F0, a01l, a01h);                              \
            LDG128_CG_OFF(p01, F1, b01l, b01h);                              \
        }                                                                    \
        u64 a10l = 0, a10h = 0, b10l = 0, b10h = 0;                          \
        if (need_y1) {                                                       \
            LDG128_CG_OFF(p10, F0, a10l, a10h);                              \
            LDG128_CG_OFF(p10, F1, b10l, b10h);                              \
        }                                                                    \
        u64 a11l = 0, a11h = 0, b11l = 0, b11h = 0;                          \
        if (need_xy) {                                                       \
            LDG128_CG_OFF(p11, F0, a11l, a11h);                              \
            LDG128_CG_OFF(p11, F1, b11l, b11h);                              \
        }                                                                    \
        const u64 tal = XLERP(a00l, a01l);                                   \
        const u64 tah = XLERP(a00h, a01h);                                   \
        const u64 tbl = XLERP(b00l, b01l);                                   \
        const u64 tbh = XLERP(b00h, b01h);                                   \
        const u64 bal = XLERP(a10l, a11l);                                   \
        const u64 bah = XLERP(a10h, a11h);                                   \
        const u64 bbl = XLERP(b10l, b11l);                                   \
        const u64 bbh = XLERP(b10h, b11h);                                   \
        const u64 ral = fma2(bal, wy2, mul2(tal, omwy2));                    \
        const u64 rah = fma2(bah, wy2, mul2(tah, omwy2));                    \
        const u64 rbl = fma2(bbl, wy2, mul2(tbl, omwy2));                    \
        const u64 rbh = fma2(bbh, wy2, mul2(tbh, omwy2));                    \
        STG128_CS_OFF(o, F0, ral, rah);                                      \
        STG128_CS_OFF(o, F1, rbl, rbh);                                      \
    }

    // Two batches (R15 structure). Byte offsets: batch0 {0, 256}, batch1
    // {512, 768} — covering floats [c*4 .. c*4+16) at +0/+64/+128/+192 floats.
    BATCH(0, 256);
    BATCH(512, 768);

#undef BATCH
#undef XLERP
}

extern "C" void kernel_launch(void* const* d_in, const int* in_sizes, int n_in,
                              void* d_out, int out_size)
{
    const float* img  = (const float*)d_in[0];
    const int*   rois = (const int*)d_in[1];
    if (in_sizes[0] == NUM_ROIS * 4) {  // defensive: swapped order
        rois = (const int*)d_in[0];
        img  = (const float*)d_in[1];
    }
    float* out = (float*)d_out;

    dim3 grid((NUM_ROIS * POOL * POOL) / CELLS_PER_BLOCK, NCHUNK);  // (6272, 4)
    roi_resize_kernel<<<grid, THREADS>>>(img, rois, out);
}